// round 16
// baseline (speedup 1.0000x reference)
#include <cuda_runtime.h>
#include <cuda_fp16.h>
#include <cstdint>

#define S_LEN  2048
#define DMODEL 1024
#define NHEAD  16
#define HDIM   64
#define MROWS  4096   // S*B
#define NPAIRS 32     // B*NHEAD
#define NX     ((size_t)MROWS * DMODEL)
#define NW     ((size_t)DMODEL * DMODEL)

// ---------------- scratch globals (allocation-free rule) ----------------
__device__ __half g_hiX[(size_t)3 * NX];    // converted q/k/v inputs (fp16 hi)
__device__ __half g_hiW[(size_t)4 * NW];    // converted Wq,Wk,Wv,Wo (hi)
__device__ __half g_hiQKV[(size_t)3 * NX];  // projected Q,K,V (fp16)
__device__ __half g_hiC[NX];                // attention context (fp16)
__device__ float  g_rowinv[NPAIRS * S_LEN];
__device__ __half g_expS[(size_t)NPAIRS * S_LEN * S_LEN];  // unnorm expS frags

// ---------------- helpers ----------------
__device__ __forceinline__ uint32_t smem_u32(const void* p) {
    uint32_t a;
    asm("{ .reg .u64 t; cvta.to.shared.u64 t, %1; cvt.u32.u64 %0, t; }" : "=r"(a) : "l"(p));
    return a;
}
__device__ __forceinline__ void ldsm4(uint32_t* r, uint32_t a) {
    asm volatile("ldmatrix.sync.aligned.m8n8.x4.shared.b16 {%0,%1,%2,%3}, [%4];"
        : "=r"(r[0]), "=r"(r[1]), "=r"(r[2]), "=r"(r[3]) : "r"(a));
}
__device__ __forceinline__ void ldsm4t(uint32_t* r, uint32_t a) {
    asm volatile("ldmatrix.sync.aligned.m8n8.x4.trans.shared.b16 {%0,%1,%2,%3}, [%4];"
        : "=r"(r[0]), "=r"(r[1]), "=r"(r[2]), "=r"(r[3]) : "r"(a));
}
__device__ __forceinline__ void mma_f16(float* d, const uint32_t* a, const uint32_t* b) {
    asm volatile("mma.sync.aligned.m16n8k16.row.col.f32.f16.f16.f32 "
        "{%0,%1,%2,%3},{%4,%5,%6,%7},{%8,%9},{%0,%1,%2,%3};"
        : "+f"(d[0]), "+f"(d[1]), "+f"(d[2]), "+f"(d[3])
        : "r"(a[0]), "r"(a[1]), "r"(a[2]), "r"(a[3]), "r"(b[0]), "r"(b[1]));
}
// 64B-row swizzle (GEMM tiles)
#define SWB(row, ch) (((row) << 6) + ((((ch) ^ (((row) >> 1) & 3))) << 4))
// 128B-row swizzle (attention tiles)
#define SWB128(row, ch) (((row) << 7) + ((((ch) ^ ((row) & 7))) << 4))

__device__ __forceinline__ uint32_t pack_h2(float a, float b) {
    __half2 h = __floats2half2_rn(a, b);
    return *(uint32_t*)&h;
}

// ---------------- batched fp32 -> fp16 (hi) conversion ----------------
struct ConvSrcs { const float* s[7]; };

__global__ void __launch_bounds__(256) conv_all(ConvSrcs p)
{
    const int b = blockIdx.x;
    int t; size_t eb;
    __half* dst;
    if (b < 12288) {
        t = b >> 12;
        eb = (size_t)(b & 4095) * 1024;
        dst = g_hiX + (size_t)t * NX;
    } else {
        const int w = b - 12288;
        t = 3 + (w >> 10);
        eb = (size_t)(w & 1023) * 1024;
        dst = g_hiW + (size_t)(t - 3) * NW;
    }
    const size_t i = eb + (size_t)threadIdx.x * 4;
    float4 v = *(const float4*)(p.s[t] + i);
    *(uint2*)(dst + i) = make_uint2(pack_h2(v.x, v.y), pack_h2(v.z, v.w));
}

// ---------------------------------------------------------------------------
// mma.sync fp16 1-term GEMM (proven 128 regs / 2 blocks per SM)
// ---------------------------------------------------------------------------
template <bool SPLIT>
__device__ __forceinline__ void gemm_mma_core(
    const __half* __restrict__ Ahi, const __half* __restrict__ Whi,
    const float* __restrict__ bias, float* __restrict__ Cf,
    __half* __restrict__ Chi)
{
    constexpr int W_OFF = 8192;
    constexpr int BUFSZ = 16384;
    __shared__ char smbuf[2 * BUFSZ];
    const int tid = threadIdx.x, lane = tid & 31, wid = tid >> 5;
    const int warpM = wid & 3, warpN = wid >> 2;
    const int row0 = blockIdx.y * 128, col0 = blockIdx.x * 128;
    const uint32_t sb = smem_u32(smbuf);

    const int grow = tid >> 2, gch = tid & 3;
    const size_t aoff0 = (size_t)(row0 + grow) * (DMODEL * 2) + gch * 16;
    const size_t aoff1 = aoff0 + (size_t)64 * (DMODEL * 2);
    const size_t woff0 = (size_t)(col0 + grow) * (DMODEL * 2) + gch * 16;
    const size_t woff1 = woff0 + (size_t)64 * (DMODEL * 2);
    const uint32_t d0 = SWB(grow, gch);
    const uint32_t d1 = SWB(grow + 64, gch);

    float acc[2][8][4];
#pragma unroll
    for (int mt = 0; mt < 2; mt++)
#pragma unroll
        for (int nt = 0; nt < 8; nt++)
#pragma unroll
            for (int e = 0; e < 4; e++) acc[mt][nt][e] = 0.f;

    uint4 pre[4];
    pre[0] = *(const uint4*)((const char*)Ahi + aoff0);
    pre[1] = *(const uint4*)((const char*)Ahi + aoff1);
    pre[2] = *(const uint4*)((const char*)Whi + woff0);
    pre[3] = *(const uint4*)((const char*)Whi + woff1);

    const int arowl = warpM * 32 + (lane & 7) + ((lane >> 3) & 1) * 8;
    const int achl  = (lane >> 4) & 1;
    const int brow8 = (lane & 7) + ((lane >> 4) & 1) * 8;
    const int bchl  = (lane >> 3) & 1;

    int buf = 0;
    for (int c = 0; c < 32; c++) {
        char* base = smbuf + buf * BUFSZ;
        *(uint4*)(base + 0     + d0) = pre[0];
        *(uint4*)(base + 0     + d1) = pre[1];
        *(uint4*)(base + W_OFF + d0) = pre[2];
        *(uint4*)(base + W_OFF + d1) = pre[3];
        __syncthreads();

        if (c + 1 < 32) {
            const size_t cb = (size_t)(c + 1) * 64;
            pre[0] = *(const uint4*)((const char*)Ahi + aoff0 + cb);
            pre[1] = *(const uint4*)((const char*)Ahi + aoff1 + cb);
            pre[2] = *(const uint4*)((const char*)Whi + woff0 + cb);
            pre[3] = *(const uint4*)((const char*)Whi + woff1 + cb);
        }

        const uint32_t bb = sb + buf * BUFSZ;
#pragma unroll
        for (int ks = 0; ks < 2; ks++) {
            uint32_t a_hi[2][4];
#pragma unroll
            for (int mt = 0; mt < 2; mt++)
                ldsm4(a_hi[mt], bb + SWB(arowl + mt * 16, ks * 2 + achl));
#pragma unroll
            for (int np = 0; np < 4; np++) {
                uint32_t bh4[4];
                ldsm4(bh4, bb + W_OFF + SWB(warpN * 64 + np * 16 + brow8, ks * 2 + bchl));
#pragma unroll
                for (int mt = 0; mt < 2; mt++) {
                    mma_f16(acc[mt][np * 2 + 0], a_hi[mt], &bh4[0]);
                    mma_f16(acc[mt][np * 2 + 1], a_hi[mt], &bh4[2]);
                }
            }
        }
        buf ^= 1;
    }

#pragma unroll
    for (int mt = 0; mt < 2; mt++) {
        const int r = row0 + warpM * 32 + mt * 16 + (lane >> 2);
#pragma unroll
        for (int nt = 0; nt < 8; nt++) {
            const int col = col0 + warpN * 64 + nt * 8 + (lane & 3) * 2;
            const float b0 = bias[col], b1 = bias[col + 1];
            const float o0 = acc[mt][nt][0] + b0, o1 = acc[mt][nt][1] + b1;
            const float o2 = acc[mt][nt][2] + b0, o3 = acc[mt][nt][3] + b1;
            if (SPLIT) {
                *(uint32_t*)&Chi[(size_t)r * DMODEL + col]       = pack_h2(o0, o1);
                *(uint32_t*)&Chi[(size_t)(r + 8) * DMODEL + col] = pack_h2(o2, o3);
            } else {
                *(float2*)&Cf[(size_t)r * DMODEL + col]       = make_float2(o0, o1);
                *(float2*)&Cf[(size_t)(r + 8) * DMODEL + col] = make_float2(o2, o3);
            }
        }
    }
}

__global__ void __launch_bounds__(256, 2) qkv_mma(
    const float* __restrict__ bq, const float* __restrict__ bk, const float* __restrict__ bv)
{
    const int z = blockIdx.z;
    const float* bias = (z == 0) ? bq : (z == 1) ? bk : bv;
    gemm_mma_core<true>(g_hiX + z * NX, g_hiW + z * NW, bias, nullptr, g_hiQKV + z * NX);
}

__global__ void __launch_bounds__(256, 2) out_mma(
    const float* __restrict__ bo, float* __restrict__ C)
{
    gemm_mma_core<false>(g_hiC, g_hiW + 3 * NW, bo, C, nullptr);
}

// ---------------------------------------------------------------------------
// Fused single-pass attention (R15, passing) — now takes a pair offset so the
// grid can be chunked for pipelined overlap with norm_attn.
// ---------------------------------------------------------------------------
#define ATT_SMEM 49152

__global__ void __launch_bounds__(256, 2) attn_fused(int pair0)
{
    extern __shared__ char sm[];
    const uint32_t sQh = smem_u32(sm);

    const int tid = threadIdx.x, lane = tid & 31, wid = tid >> 5;
    const int p = pair0 + blockIdx.y, bb = p >> 4, h = p & 15;
    const int row0 = blockIdx.x * 128;
    uint4* const sbase = (uint4*)g_expS + (size_t)(p * 16 + blockIdx.x) * 32768;

    const int srow0 = tid >> 3,         sch0 = tid & 7;
    const int srow1 = (tid + 256) >> 3, sch1 = (tid + 256) & 7;
    const uint32_t sso0 = SWB128(srow0, sch0);
    const uint32_t sso1 = SWB128(srow1, sch1);

#pragma unroll
    for (int ps = 0; ps < 4; ps++) {
        const int u = tid + ps * 256;
        const int row = u >> 3, ch = u & 7;
        const size_t ge = (size_t)(bb * S_LEN + row0 + row) * DMODEL + h * HDIM + ch * 8;
        *(uint4*)(sm + SWB128(row, ch)) = *(const uint4*)(g_hiQKV + ge);
    }
    {
        const size_t kg0 = NX     + (size_t)(bb * S_LEN + srow0) * DMODEL + h * HDIM + sch0 * 8;
        const size_t kg1 = NX     + (size_t)(bb * S_LEN + srow1) * DMODEL + h * HDIM + sch1 * 8;
        const size_t vg0 = 2 * NX + (size_t)(bb * S_LEN + srow0) * DMODEL + h * HDIM + sch0 * 8;
        const size_t vg1 = 2 * NX + (size_t)(bb * S_LEN + srow1) * DMODEL + h * HDIM + sch1 * 8;
        *(uint4*)(sm + 16384 + sso0) = *(const uint4*)(g_hiQKV + kg0);
        *(uint4*)(sm + 16384 + sso1) = *(const uint4*)(g_hiQKV + kg1);
        *(uint4*)(sm + 32768 + sso0) = *(const uint4*)(g_hiQKV + vg0);
        *(uint4*)(sm + 32768 + sso1) = *(const uint4*)(g_hiQKV + vg1);
    }
    __syncthreads();

    const int arowl = wid * 16 + (lane & 7) + ((lane >> 3) & 1) * 8;
    const int achl  = (lane >> 4) & 1;
    const int brow8 = (lane & 7) + ((lane >> 4) & 1) * 8;
    const int bchl  = (lane >> 3) & 1;
    const int vrowl = (lane & 7) + ((lane >> 3) & 1) * 8;
    const int vtog  = (lane >> 4) & 1;
    const float sc = 0.125f;

    float ctx[8][4];
#pragma unroll
    for (int nt = 0; nt < 8; nt++)
#pragma unroll
        for (int e = 0; e < 4; e++) ctx[nt][e] = 0.f;
    float rs0 = 0.f, rs1 = 0.f;

    for (int c = 0; c < 32; c++) {
        uint4 k0, k1, v0, v1;
        if (c + 1 < 32) {
            const int c1 = (c + 1) * 64;
            k0 = *(const uint4*)(g_hiQKV + NX     + (size_t)(bb * S_LEN + c1 + srow0) * DMODEL + h * HDIM + sch0 * 8);
            k1 = *(const uint4*)(g_hiQKV + NX     + (size_t)(bb * S_LEN + c1 + srow1) * DMODEL + h * HDIM + sch1 * 8);
            v0 = *(const uint4*)(g_hiQKV + 2 * NX + (size_t)(bb * S_LEN + c1 + srow0) * DMODEL + h * HDIM + sch0 * 8);
            v1 = *(const uint4*)(g_hiQKV + 2 * NX + (size_t)(bb * S_LEN + c1 + srow1) * DMODEL + h * HDIM + sch1 * 8);
        }
        const uint32_t kcur = sQh + 16384 + (c & 1) * 8192;
        const uint32_t vcur = sQh + 32768 + (c & 1) * 8192;

        float acc[8][4];
#pragma unroll
        for (int nt = 0; nt < 8; nt++)
#pragma unroll
            for (int e = 0; e < 4; e++) acc[nt][e] = 0.f;
#pragma unroll
        for (int ks = 0; ks < 4; ks++) {
            uint32_t a4[4];
            ldsm4(a4, sQh + SWB128(arowl, ks * 2 + achl));
#pragma unroll
            for (int np = 0; np < 4; np++) {
                uint32_t bh4[4];
                ldsm4(bh4, kcur + SWB128(np * 16 + brow8, ks * 2 + bchl));
                mma_f16(acc[np * 2 + 0], a4, &bh4[0]);
                mma_f16(acc[np * 2 + 1], a4, &bh4[2]);
            }
        }

        uint32_t frag[16];
#pragma unroll
        for (int nt = 0; nt < 8; nt++) {
            const float e0 = __expf(acc[nt][0] * sc);
            const float e1 = __expf(acc[nt][1] * sc);
            const float e2 = __expf(acc[nt][2] * sc);
            const float e3 = __expf(acc[nt][3] * sc);
            rs0 += e0 + e1;
            rs1 += e2 + e3;
            frag[nt * 2 + 0] = pack_h2(e0, e1);
            frag[nt * 2 + 1] = pack_h2(e2, e3);
        }
        uint4* sp = sbase + (size_t)c * 1024 + tid;
#pragma unroll
        for (int j = 0; j < 4; j++)
            sp[j * 256] = *(uint4*)(frag + j * 4);

        if (c + 1 < 32) {
            char* kb = sm + 16384 + ((c + 1) & 1) * 8192;
            char* vb = sm + 32768 + ((c + 1) & 1) * 8192;
            *(uint4*)(kb + sso0) = k0;
            *(uint4*)(kb + sso1) = k1;
            *(uint4*)(vb + sso0) = v0;
            *(uint4*)(vb + sso1) = v1;
        }

#pragma unroll
        for (int kg = 0; kg < 4; kg++) {
            const uint32_t* ah = frag + kg * 4;
#pragma unroll
            for (int ld = 0; ld < 4; ld++) {
                uint32_t bh4[4];
                ldsm4t(bh4, vcur + SWB128(kg * 16 + vrowl, ld * 2 + vtog));
                mma_f16(ctx[ld * 2 + 0], ah, &bh4[0]);
                mma_f16(ctx[ld * 2 + 1], ah, &bh4[2]);
            }
        }
        __syncthreads();
    }

    rs0 += __shfl_xor_sync(0xffffffffu, rs0, 1);
    rs0 += __shfl_xor_sync(0xffffffffu, rs0, 2);
    rs1 += __shfl_xor_sync(0xffffffffu, rs1, 1);
    rs1 += __shfl_xor_sync(0xffffffffu, rs1, 2);
    const float rinv0 = 1.0f / rs0;
    const float rinv1 = 1.0f / rs1;
    const int r0 = wid * 16 + (lane >> 2);
    if ((lane & 3) == 0) {
        g_rowinv[p * S_LEN + row0 + r0]     = rinv0;
        g_rowinv[p * S_LEN + row0 + r0 + 8] = rinv1;
    }
    const size_t gr0 = (size_t)(bb * S_LEN + row0 + r0) * DMODEL + h * HDIM;
    const size_t gr1 = gr0 + (size_t)8 * DMODEL;
#pragma unroll
    for (int nt = 0; nt < 8; nt++) {
        const int col = nt * 8 + (lane & 3) * 2;
        *(uint32_t*)&g_hiC[gr0 + col] = pack_h2(ctx[nt][0] * rinv0, ctx[nt][1] * rinv0);
        *(uint32_t*)&g_hiC[gr1 + col] = pack_h2(ctx[nt][2] * rinv1, ctx[nt][3] * rinv1);
    }
}

// ---------------------------------------------------------------------------
// Streaming normalize (pair-chunked): read expS frags, scale by rinv, write
// fp32 attn. grid = (pairs*16, 4 chunk-groups).
// ---------------------------------------------------------------------------
__global__ void __launch_bounds__(256) norm_attn(int pair0, float* __restrict__ attn)
{
    const int p = pair0 + (blockIdx.x >> 4), rb = blockIdx.x & 15;
    const int bx = p * 16 + rb;
    const int row0 = rb * 128;
    const int tid = threadIdx.x, lane = tid & 31, wid = tid >> 5;
    const uint4* const sbase = (const uint4*)g_expS + (size_t)bx * 32768;

    const int r0 = wid * 16 + (lane >> 2);
    const __half2 h0 = __float2half2_rn(g_rowinv[p * S_LEN + row0 + r0]);
    const __half2 h1 = __float2half2_rn(g_rowinv[p * S_LEN + row0 + r0 + 8]);
    const size_t ga0 = ((size_t)(p * S_LEN) + row0 + r0) * S_LEN;
    const size_t ga1 = ga0 + (size_t)8 * S_LEN;

    const int cbeg = blockIdx.y * 8, cend = cbeg + 8;
    for (int c = cbeg; c < cend; c++) {
        uint32_t frag[16];
        const uint4* sp = sbase + (size_t)c * 1024 + tid;
#pragma unroll
        for (int j = 0; j < 4; j++)
            *(uint4*)(frag + j * 4) = sp[j * 256];
        const int c0 = c * 64;
#pragma unroll
        for (int nt = 0; nt < 8; nt++) {
            const int col = c0 + nt * 8 + (lane & 3) * 2;
            __half2 s0 = __hmul2(*(__half2*)&frag[nt * 2 + 0], h0);
            __half2 s1 = __hmul2(*(__half2*)&frag[nt * 2 + 1], h1);
            *(float2*)&attn[ga0 + col] = __half22float2(s0);
            *(float2*)&attn[ga1 + col] = __half22float2(s1);
        }
    }
}

// ---------------------------------------------------------------------------
extern "C" void kernel_launch(void* const* d_in, const int* in_sizes, int n_in,
                              void* d_out, int out_size) {
    const float* query = (const float*)d_in[0];
    const float* key_  = (const float*)d_in[1];
    const float* value = (const float*)d_in[2];
    const float* Wq = (const float*)d_in[3];
    const float* bq = (const float*)d_in[4];
    const float* Wk = (const float*)d_in[5];
    const float* bk = (const float*)d_in[6];
    const float* Wv = (const float*)d_in[7];
    const float* bv = (const float*)d_in[8];
    const float* Wo = (const float*)d_in[9];
    const float* bo = (const float*)d_in[10];

    float* outp = (float*)d_out;
    float* attn = outp + NX;          // tuple output: (out, attn)

    static cudaStream_t s1 = nullptr;
    static cudaEvent_t evA[4], evJ;
    static int init_done = 0;
    if (!init_done) {
        cudaFuncSetAttribute(attn_fused, cudaFuncAttributeMaxDynamicSharedMemorySize, ATT_SMEM);
        cudaStreamCreateWithFlags(&s1, cudaStreamNonBlocking);
        for (int g = 0; g < 4; g++)
            cudaEventCreateWithFlags(&evA[g], cudaEventDisableTiming);
        cudaEventCreateWithFlags(&evJ, cudaEventDisableTiming);
        init_done = 1;
    }

    ConvSrcs cs;
    cs.s[0] = query; cs.s[1] = key_; cs.s[2] = value;
    cs.s[3] = Wq; cs.s[4] = Wk; cs.s[5] = Wv; cs.s[6] = Wo;
    conv_all<<<16384, 256>>>(cs);

    qkv_mma<<<dim3(DMODEL / 128, MROWS / 128, 3), 256>>>(bq, bk, bv);

    // pipelined attention: attn chunks on main stream, norm chunks on s1
    for (int g = 0; g < 4; g++) {
        attn_fused<<<dim3(16, 8), 256, ATT_SMEM>>>(g * 8);
        cudaEventRecord(evA[g], 0);
        cudaStreamWaitEvent(s1, evA[g], 0);
        norm_attn<<<dim3(128, 4), 256, 0, s1>>>(g * 8, attn);
    }

    out_mma<<<dim3(DMODEL / 128, MROWS / 128), 256>>>(bo, outp);

    // join s1 back into the main stream
    cudaEventRecord(evJ, s1);
    cudaStreamWaitEvent(0, evJ, 0);
}

// round 17
// speedup vs baseline: 1.2581x; 1.2581x over previous
#include <cuda_runtime.h>
#include <cuda_fp16.h>
#include <cstdint>

#define S_LEN  2048
#define DMODEL 1024
#define NHEAD  16
#define HDIM   64
#define MROWS  4096   // S*B
#define NPAIRS 32     // B*NHEAD
#define NX     ((size_t)MROWS * DMODEL)
#define NW     ((size_t)DMODEL * DMODEL)

// ---------------- scratch globals (allocation-free rule) ----------------
__device__ __half g_hiX[(size_t)3 * NX];    // converted q/k/v inputs (fp16 hi)
__device__ __half g_hiW[(size_t)4 * NW];    // converted Wq,Wk,Wv,Wo (hi)
__device__ __half g_hiQKV[(size_t)3 * NX];  // projected Q,K,V (fp16)
__device__ __half g_hiC[NX];                // attention context (fp16)
__device__ float  g_rowinv[NPAIRS * S_LEN];
__device__ __half g_expS[(size_t)NPAIRS * S_LEN * S_LEN];  // unnorm expS frags

// ---------------- helpers ----------------
__device__ __forceinline__ uint32_t smem_u32(const void* p) {
    uint32_t a;
    asm("{ .reg .u64 t; cvta.to.shared.u64 t, %1; cvt.u32.u64 %0, t; }" : "=r"(a) : "l"(p));
    return a;
}
__device__ __forceinline__ void ldsm4(uint32_t* r, uint32_t a) {
    asm volatile("ldmatrix.sync.aligned.m8n8.x4.shared.b16 {%0,%1,%2,%3}, [%4];"
        : "=r"(r[0]), "=r"(r[1]), "=r"(r[2]), "=r"(r[3]) : "r"(a));
}
__device__ __forceinline__ void ldsm4t(uint32_t* r, uint32_t a) {
    asm volatile("ldmatrix.sync.aligned.m8n8.x4.trans.shared.b16 {%0,%1,%2,%3}, [%4];"
        : "=r"(r[0]), "=r"(r[1]), "=r"(r[2]), "=r"(r[3]) : "r"(a));
}
__device__ __forceinline__ void mma_f16(float* d, const uint32_t* a, const uint32_t* b) {
    asm volatile("mma.sync.aligned.m16n8k16.row.col.f32.f16.f16.f32 "
        "{%0,%1,%2,%3},{%4,%5,%6,%7},{%8,%9},{%0,%1,%2,%3};"
        : "+f"(d[0]), "+f"(d[1]), "+f"(d[2]), "+f"(d[3])
        : "r"(a[0]), "r"(a[1]), "r"(a[2]), "r"(a[3]), "r"(b[0]), "r"(b[1]));
}
// 64B-row swizzle (GEMM tiles)
#define SWB(row, ch) (((row) << 6) + ((((ch) ^ (((row) >> 1) & 3))) << 4))
// 128B-row swizzle (attention tiles)
#define SWB128(row, ch) (((row) << 7) + ((((ch) ^ ((row) & 7))) << 4))

__device__ __forceinline__ uint32_t pack_h2(float a, float b) {
    __half2 h = __floats2half2_rn(a, b);
    return *(uint32_t*)&h;
}

// ---------------- batched fp32 -> fp16 (hi) conversion ----------------
struct ConvSrcs { const float* s[7]; };

__global__ void __launch_bounds__(256) conv_all(ConvSrcs p)
{
    const int b = blockIdx.x;
    int t; size_t eb;
    __half* dst;
    if (b < 12288) {
        t = b >> 12;
        eb = (size_t)(b & 4095) * 1024;
        dst = g_hiX + (size_t)t * NX;
    } else {
        const int w = b - 12288;
        t = 3 + (w >> 10);
        eb = (size_t)(w & 1023) * 1024;
        dst = g_hiW + (size_t)(t - 3) * NW;
    }
    const size_t i = eb + (size_t)threadIdx.x * 4;
    float4 v = *(const float4*)(p.s[t] + i);
    *(uint2*)(dst + i) = make_uint2(pack_h2(v.x, v.y), pack_h2(v.z, v.w));
}

// ---------------------------------------------------------------------------
// mma.sync fp16 1-term GEMM (proven 128 regs / 2 blocks per SM)
// ---------------------------------------------------------------------------
template <bool SPLIT>
__device__ __forceinline__ void gemm_mma_core(
    const __half* __restrict__ Ahi, const __half* __restrict__ Whi,
    const float* __restrict__ bias, float* __restrict__ Cf,
    __half* __restrict__ Chi)
{
    constexpr int W_OFF = 8192;
    constexpr int BUFSZ = 16384;
    __shared__ char smbuf[2 * BUFSZ];
    const int tid = threadIdx.x, lane = tid & 31, wid = tid >> 5;
    const int warpM = wid & 3, warpN = wid >> 2;
    const int row0 = blockIdx.y * 128, col0 = blockIdx.x * 128;
    const uint32_t sb = smem_u32(smbuf);

    const int grow = tid >> 2, gch = tid & 3;
    const size_t aoff0 = (size_t)(row0 + grow) * (DMODEL * 2) + gch * 16;
    const size_t aoff1 = aoff0 + (size_t)64 * (DMODEL * 2);
    const size_t woff0 = (size_t)(col0 + grow) * (DMODEL * 2) + gch * 16;
    const size_t woff1 = woff0 + (size_t)64 * (DMODEL * 2);
    const uint32_t d0 = SWB(grow, gch);
    const uint32_t d1 = SWB(grow + 64, gch);

    float acc[2][8][4];
#pragma unroll
    for (int mt = 0; mt < 2; mt++)
#pragma unroll
        for (int nt = 0; nt < 8; nt++)
#pragma unroll
            for (int e = 0; e < 4; e++) acc[mt][nt][e] = 0.f;

    uint4 pre[4];
    pre[0] = *(const uint4*)((const char*)Ahi + aoff0);
    pre[1] = *(const uint4*)((const char*)Ahi + aoff1);
    pre[2] = *(const uint4*)((const char*)Whi + woff0);
    pre[3] = *(const uint4*)((const char*)Whi + woff1);

    const int arowl = warpM * 32 + (lane & 7) + ((lane >> 3) & 1) * 8;
    const int achl  = (lane >> 4) & 1;
    const int brow8 = (lane & 7) + ((lane >> 4) & 1) * 8;
    const int bchl  = (lane >> 3) & 1;

    int buf = 0;
    for (int c = 0; c < 32; c++) {
        char* base = smbuf + buf * BUFSZ;
        *(uint4*)(base + 0     + d0) = pre[0];
        *(uint4*)(base + 0     + d1) = pre[1];
        *(uint4*)(base + W_OFF + d0) = pre[2];
        *(uint4*)(base + W_OFF + d1) = pre[3];
        __syncthreads();

        if (c + 1 < 32) {
            const size_t cb = (size_t)(c + 1) * 64;
            pre[0] = *(const uint4*)((const char*)Ahi + aoff0 + cb);
            pre[1] = *(const uint4*)((const char*)Ahi + aoff1 + cb);
            pre[2] = *(const uint4*)((const char*)Whi + woff0 + cb);
            pre[3] = *(const uint4*)((const char*)Whi + woff1 + cb);
        }

        const uint32_t bb = sb + buf * BUFSZ;
#pragma unroll
        for (int ks = 0; ks < 2; ks++) {
            uint32_t a_hi[2][4];
#pragma unroll
            for (int mt = 0; mt < 2; mt++)
                ldsm4(a_hi[mt], bb + SWB(arowl + mt * 16, ks * 2 + achl));
#pragma unroll
            for (int np = 0; np < 4; np++) {
                uint32_t bh4[4];
                ldsm4(bh4, bb + W_OFF + SWB(warpN * 64 + np * 16 + brow8, ks * 2 + bchl));
#pragma unroll
                for (int mt = 0; mt < 2; mt++) {
                    mma_f16(acc[mt][np * 2 + 0], a_hi[mt], &bh4[0]);
                    mma_f16(acc[mt][np * 2 + 1], a_hi[mt], &bh4[2]);
                }
            }
        }
        buf ^= 1;
    }

#pragma unroll
    for (int mt = 0; mt < 2; mt++) {
        const int r = row0 + warpM * 32 + mt * 16 + (lane >> 2);
#pragma unroll
        for (int nt = 0; nt < 8; nt++) {
            const int col = col0 + warpN * 64 + nt * 8 + (lane & 3) * 2;
            const float b0 = bias[col], b1 = bias[col + 1];
            const float o0 = acc[mt][nt][0] + b0, o1 = acc[mt][nt][1] + b1;
            const float o2 = acc[mt][nt][2] + b0, o3 = acc[mt][nt][3] + b1;
            if (SPLIT) {
                *(uint32_t*)&Chi[(size_t)r * DMODEL + col]       = pack_h2(o0, o1);
                *(uint32_t*)&Chi[(size_t)(r + 8) * DMODEL + col] = pack_h2(o2, o3);
            } else {
                *(float2*)&Cf[(size_t)r * DMODEL + col]       = make_float2(o0, o1);
                *(float2*)&Cf[(size_t)(r + 8) * DMODEL + col] = make_float2(o2, o3);
            }
        }
    }
}

__global__ void __launch_bounds__(256, 2) qkv_mma(
    const float* __restrict__ bq, const float* __restrict__ bk, const float* __restrict__ bv)
{
    const int z = blockIdx.z;
    const float* bias = (z == 0) ? bq : (z == 1) ? bk : bv;
    gemm_mma_core<true>(g_hiX + z * NX, g_hiW + z * NW, bias, nullptr, g_hiQKV + z * NX);
}

__global__ void __launch_bounds__(256, 2) out_mma(
    const float* __restrict__ bo, float* __restrict__ C)
{
    gemm_mma_core<false>(g_hiC, g_hiW + 3 * NW, bo, C, nullptr);
}

// ---------------------------------------------------------------------------
// Fused single-pass attention (R15 design, passing at 423.6us).
// ---------------------------------------------------------------------------
#define ATT_SMEM 49152

__global__ void __launch_bounds__(256, 2) attn_fused()
{
    extern __shared__ char sm[];
    const uint32_t sQh = smem_u32(sm);

    const int tid = threadIdx.x, lane = tid & 31, wid = tid >> 5;
    const int p = blockIdx.y, bb = p >> 4, h = p & 15;
    const int row0 = blockIdx.x * 128;
    uint4* const sbase = (uint4*)g_expS + (size_t)(p * 16 + blockIdx.x) * 32768;

    const int srow0 = tid >> 3,         sch0 = tid & 7;
    const int srow1 = (tid + 256) >> 3, sch1 = (tid + 256) & 7;
    const uint32_t sso0 = SWB128(srow0, sch0);
    const uint32_t sso1 = SWB128(srow1, sch1);

#pragma unroll
    for (int ps = 0; ps < 4; ps++) {
        const int u = tid + ps * 256;
        const int row = u >> 3, ch = u & 7;
        const size_t ge = (size_t)(bb * S_LEN + row0 + row) * DMODEL + h * HDIM + ch * 8;
        *(uint4*)(sm + SWB128(row, ch)) = *(const uint4*)(g_hiQKV + ge);
    }
    {
        const size_t kg0 = NX     + (size_t)(bb * S_LEN + srow0) * DMODEL + h * HDIM + sch0 * 8;
        const size_t kg1 = NX     + (size_t)(bb * S_LEN + srow1) * DMODEL + h * HDIM + sch1 * 8;
        const size_t vg0 = 2 * NX + (size_t)(bb * S_LEN + srow0) * DMODEL + h * HDIM + sch0 * 8;
        const size_t vg1 = 2 * NX + (size_t)(bb * S_LEN + srow1) * DMODEL + h * HDIM + sch1 * 8;
        *(uint4*)(sm + 16384 + sso0) = *(const uint4*)(g_hiQKV + kg0);
        *(uint4*)(sm + 16384 + sso1) = *(const uint4*)(g_hiQKV + kg1);
        *(uint4*)(sm + 32768 + sso0) = *(const uint4*)(g_hiQKV + vg0);
        *(uint4*)(sm + 32768 + sso1) = *(const uint4*)(g_hiQKV + vg1);
    }
    __syncthreads();

    const int arowl = wid * 16 + (lane & 7) + ((lane >> 3) & 1) * 8;
    const int achl  = (lane >> 4) & 1;
    const int brow8 = (lane & 7) + ((lane >> 4) & 1) * 8;
    const int bchl  = (lane >> 3) & 1;
    const int vrowl = (lane & 7) + ((lane >> 3) & 1) * 8;
    const int vtog  = (lane >> 4) & 1;
    const float sc = 0.125f;

    float ctx[8][4];
#pragma unroll
    for (int nt = 0; nt < 8; nt++)
#pragma unroll
        for (int e = 0; e < 4; e++) ctx[nt][e] = 0.f;
    float rs0 = 0.f, rs1 = 0.f;

    for (int c = 0; c < 32; c++) {
        uint4 k0, k1, v0, v1;
        if (c + 1 < 32) {
            const int c1 = (c + 1) * 64;
            k0 = *(const uint4*)(g_hiQKV + NX     + (size_t)(bb * S_LEN + c1 + srow0) * DMODEL + h * HDIM + sch0 * 8);
            k1 = *(const uint4*)(g_hiQKV + NX     + (size_t)(bb * S_LEN + c1 + srow1) * DMODEL + h * HDIM + sch1 * 8);
            v0 = *(const uint4*)(g_hiQKV + 2 * NX + (size_t)(bb * S_LEN + c1 + srow0) * DMODEL + h * HDIM + sch0 * 8);
            v1 = *(const uint4*)(g_hiQKV + 2 * NX + (size_t)(bb * S_LEN + c1 + srow1) * DMODEL + h * HDIM + sch1 * 8);
        }
        const uint32_t kcur = sQh + 16384 + (c & 1) * 8192;
        const uint32_t vcur = sQh + 32768 + (c & 1) * 8192;

        float acc[8][4];
#pragma unroll
        for (int nt = 0; nt < 8; nt++)
#pragma unroll
            for (int e = 0; e < 4; e++) acc[nt][e] = 0.f;
#pragma unroll
        for (int ks = 0; ks < 4; ks++) {
            uint32_t a4[4];
            ldsm4(a4, sQh + SWB128(arowl, ks * 2 + achl));
#pragma unroll
            for (int np = 0; np < 4; np++) {
                uint32_t bh4[4];
                ldsm4(bh4, kcur + SWB128(np * 16 + brow8, ks * 2 + bchl));
                mma_f16(acc[np * 2 + 0], a4, &bh4[0]);
                mma_f16(acc[np * 2 + 1], a4, &bh4[2]);
            }
        }

        uint32_t frag[16];
#pragma unroll
        for (int nt = 0; nt < 8; nt++) {
            const float e0 = __expf(acc[nt][0] * sc);
            const float e1 = __expf(acc[nt][1] * sc);
            const float e2 = __expf(acc[nt][2] * sc);
            const float e3 = __expf(acc[nt][3] * sc);
            rs0 += e0 + e1;
            rs1 += e2 + e3;
            frag[nt * 2 + 0] = pack_h2(e0, e1);
            frag[nt * 2 + 1] = pack_h2(e2, e3);
        }
        uint4* sp = sbase + (size_t)c * 1024 + tid;
#pragma unroll
        for (int j = 0; j < 4; j++)
            sp[j * 256] = *(uint4*)(frag + j * 4);

        if (c + 1 < 32) {
            char* kb = sm + 16384 + ((c + 1) & 1) * 8192;
            char* vb = sm + 32768 + ((c + 1) & 1) * 8192;
            *(uint4*)(kb + sso0) = k0;
            *(uint4*)(kb + sso1) = k1;
            *(uint4*)(vb + sso0) = v0;
            *(uint4*)(vb + sso1) = v1;
        }

#pragma unroll
        for (int kg = 0; kg < 4; kg++) {
            const uint32_t* ah = frag + kg * 4;
#pragma unroll
            for (int ld = 0; ld < 4; ld++) {
                uint32_t bh4[4];
                ldsm4t(bh4, vcur + SWB128(kg * 16 + vrowl, ld * 2 + vtog));
                mma_f16(ctx[ld * 2 + 0], ah, &bh4[0]);
                mma_f16(ctx[ld * 2 + 1], ah, &bh4[2]);
            }
        }
        __syncthreads();
    }

    rs0 += __shfl_xor_sync(0xffffffffu, rs0, 1);
    rs0 += __shfl_xor_sync(0xffffffffu, rs0, 2);
    rs1 += __shfl_xor_sync(0xffffffffu, rs1, 1);
    rs1 += __shfl_xor_sync(0xffffffffu, rs1, 2);
    const float rinv0 = 1.0f / rs0;
    const float rinv1 = 1.0f / rs1;
    const int r0 = wid * 16 + (lane >> 2);
    if ((lane & 3) == 0) {
        g_rowinv[p * S_LEN + row0 + r0]     = rinv0;
        g_rowinv[p * S_LEN + row0 + r0 + 8] = rinv1;
    }
    const size_t gr0 = (size_t)(bb * S_LEN + row0 + r0) * DMODEL + h * HDIM;
    const size_t gr1 = gr0 + (size_t)8 * DMODEL;
#pragma unroll
    for (int nt = 0; nt < 8; nt++) {
        const int col = nt * 8 + (lane & 3) * 2;
        *(uint32_t*)&g_hiC[gr0 + col] = pack_h2(ctx[nt][0] * rinv0, ctx[nt][1] * rinv0);
        *(uint32_t*)&g_hiC[gr1 + col] = pack_h2(ctx[nt][2] * rinv1, ctx[nt][3] * rinv1);
    }
}

// ---------------------------------------------------------------------------
// Streaming normalize v2: coalesced frag load -> smem transpose (bank-safe
// stride 36 words) -> fp32 normalize -> fully-coalesced float4 row writes.
// grid = (512 tiles, 4 chunk-groups of 8).
// ---------------------------------------------------------------------------
__global__ void __launch_bounds__(256) norm_attn(float* __restrict__ attn)
{
    __shared__ uint32_t tile[128 * 36];
    __shared__ float rinv_s[128];
    const int bx = blockIdx.x;            // 0..511 : (p*16 + rowblock)
    const int p = bx >> 4, rb = bx & 15;
    const int row0 = rb * 128;
    const int tid = threadIdx.x, lane = tid & 31, wid = tid >> 5;
    const uint4* const sbase = (const uint4*)g_expS + (size_t)bx * 32768;

    if (tid < 128) rinv_s[tid] = g_rowinv[p * S_LEN + row0 + tid];
    const int frow   = wid * 16 + (lane >> 2);   // fragment rows frow, frow+8
    const int fcol32 = lane & 3;                 // uint32 col within nt-group
    __syncthreads();

    const int cbeg = blockIdx.y * 8, cend = cbeg + 8;
    for (int c = cbeg; c < cend; c++) {
        uint32_t frag[16];
        const uint4* sp = sbase + (size_t)c * 1024 + tid;
#pragma unroll
        for (int j = 0; j < 4; j++)
            *(uint4*)(frag + j * 4) = sp[j * 256];

        // scatter into logical layout (stride 36 words: conflict-free)
#pragma unroll
        for (int nt = 0; nt < 8; nt++) {
            tile[frow * 36       + nt * 4 + fcol32] = frag[nt * 2 + 0];
            tile[(frow + 8) * 36 + nt * 4 + fcol32] = frag[nt * 2 + 1];
        }
        __syncthreads();

        // row-major readback, fp32 normalize, coalesced float4 writes
        const int c0 = c * 64;
#pragma unroll
        for (int it = 0; it < 8; it++) {
            const int flat = tid + it * 256;       // 0..2047 over 128x16 f4s
            const int row = flat >> 4, f4 = flat & 15;
            const uint32_t u0 = tile[row * 36 + f4 * 2];
            const uint32_t u1 = tile[row * 36 + f4 * 2 + 1];
            const float ri = rinv_s[row];
            float2 fa = __half22float2(*(const __half2*)&u0);
            float2 fb = __half22float2(*(const __half2*)&u1);
            *(float4*)&attn[((size_t)(p * S_LEN) + row0 + row) * S_LEN + c0 + f4 * 4]
                = make_float4(fa.x * ri, fa.y * ri, fb.x * ri, fb.y * ri);
        }
        __syncthreads();
    }
}

// ---------------------------------------------------------------------------
extern "C" void kernel_launch(void* const* d_in, const int* in_sizes, int n_in,
                              void* d_out, int out_size) {
    const float* query = (const float*)d_in[0];
    const float* key_  = (const float*)d_in[1];
    const float* value = (const float*)d_in[2];
    const float* Wq = (const float*)d_in[3];
    const float* bq = (const float*)d_in[4];
    const float* Wk = (const float*)d_in[5];
    const float* bk = (const float*)d_in[6];
    const float* Wv = (const float*)d_in[7];
    const float* bv = (const float*)d_in[8];
    const float* Wo = (const float*)d_in[9];
    const float* bo = (const float*)d_in[10];

    float* outp = (float*)d_out;
    float* attn = outp + NX;          // tuple output: (out, attn)

    static int attr_set = 0;
    if (!attr_set) {
        cudaFuncSetAttribute(attn_fused, cudaFuncAttributeMaxDynamicSharedMemorySize, ATT_SMEM);
        attr_set = 1;
    }

    ConvSrcs cs;
    cs.s[0] = query; cs.s[1] = key_; cs.s[2] = value;
    cs.s[3] = Wq; cs.s[4] = Wk; cs.s[5] = Wv; cs.s[6] = Wo;
    conv_all<<<16384, 256>>>(cs);

    qkv_mma<<<dim3(DMODEL / 128, MROWS / 128, 3), 256>>>(bq, bk, bv);
    attn_fused<<<dim3(S_LEN / 128, NPAIRS), 256, ATT_SMEM>>>();
    out_mma<<<dim3(DMODEL / 128, MROWS / 128), 256>>>(bo, outp);
    norm_attn<<<dim3(512, 4), 256>>>(attn);
}